// round 3
// baseline (speedup 1.0000x reference)
#include <cuda_runtime.h>

// Per-quaternion L2 normalize: (65536, 1024) fp32 = 2^24 quats. Pure HBM
// stream, 512 MiB. R1: MLP1x2 -> 5955 GB/s. R2: MLP=4 -> 6479 GB/s (81%).
// R3: MLP_p1=8 front-batched float4 loads/thread, streaming .cs hints.

static __device__ __forceinline__ float4 norm_quat(float4 v) {
    float s = v.x * v.x + v.y * v.y + v.z * v.z + v.w * v.w;
    float inv = (s == 0.0f) ? 1.0f : rsqrtf(s);
    v.x *= inv; v.y *= inv; v.z *= inv; v.w *= inv;
    return v;
}

__global__ void __launch_bounds__(256)
quat_normalize_kernel(const float4* __restrict__ in,
                      float4* __restrict__ out) {
    const int T = 256;
    int base = blockIdx.x * (T * 8) + threadIdx.x;

    // 8 independent, warp-coalesced 16B loads in flight per thread.
    float4 v0 = __ldcs(&in[base]);
    float4 v1 = __ldcs(&in[base + T]);
    float4 v2 = __ldcs(&in[base + 2 * T]);
    float4 v3 = __ldcs(&in[base + 3 * T]);
    float4 v4 = __ldcs(&in[base + 4 * T]);
    float4 v5 = __ldcs(&in[base + 5 * T]);
    float4 v6 = __ldcs(&in[base + 6 * T]);
    float4 v7 = __ldcs(&in[base + 7 * T]);

    v0 = norm_quat(v0);
    v1 = norm_quat(v1);
    v2 = norm_quat(v2);
    v3 = norm_quat(v3);
    v4 = norm_quat(v4);
    v5 = norm_quat(v5);
    v6 = norm_quat(v6);
    v7 = norm_quat(v7);

    __stcs(&out[base],         v0);
    __stcs(&out[base + T],     v1);
    __stcs(&out[base + 2 * T], v2);
    __stcs(&out[base + 3 * T], v3);
    __stcs(&out[base + 4 * T], v4);
    __stcs(&out[base + 5 * T], v5);
    __stcs(&out[base + 6 * T], v6);
    __stcs(&out[base + 7 * T], v7);
}

// Bounds-checked fallback for non-multiple sizes (unused for 2^24 quats).
__global__ void __launch_bounds__(256)
quat_normalize_tail_kernel(const float4* __restrict__ in,
                           float4* __restrict__ out,
                           int n_quat) {
    int i = blockIdx.x * blockDim.x + threadIdx.x;
    if (i < n_quat) out[i] = norm_quat(__ldcs(&in[i]));
}

extern "C" void kernel_launch(void* const* d_in, const int* in_sizes, int n_in,
                              void* d_out, int out_size) {
    const float4* x = (const float4*)d_in[0];
    float4* y = (float4*)d_out;
    int n_quat = in_sizes[0] / 4;   // 16,777,216

    const int threads = 256;
    const int per_block = threads * 8;  // 2048 quats/block

    if (n_quat % per_block == 0) {
        quat_normalize_kernel<<<n_quat / per_block, threads>>>(x, y);  // 8192 blocks
    } else {
        int main_blocks = n_quat / per_block;
        if (main_blocks > 0)
            quat_normalize_kernel<<<main_blocks, threads>>>(x, y);
        int done = main_blocks * per_block;
        int rem = n_quat - done;
        if (rem > 0)
            quat_normalize_tail_kernel<<<(rem + threads - 1) / threads, threads>>>(
                x + done, y + done, rem);
    }
}

// round 4
// speedup vs baseline: 1.0012x; 1.0012x over previous
#include <cuda_runtime.h>

// Per-quaternion L2 normalize: (65536, 1024) fp32 = 2^24 quats. Pure HBM
// stream, 512 MiB mandatory traffic.
// R1 MLP2:       5955 GB/s (75.2%)
// R2 MLP4 T256:  6479 GB/s (81.8%)  <- best
// R3 MLP8 T256:  6324 GB/s (79.8%)  regs 40, occ 62% -> regression
// R4: MLP4 again, T=512 (better wave packing), stores interleaved right
//     after each quat's math to keep live ranges short (regs ~31).

static __device__ __forceinline__ float4 norm_quat(float4 v) {
    float s = v.x * v.x + v.y * v.y + v.z * v.z + v.w * v.w;
    float inv = (s == 0.0f) ? 1.0f : rsqrtf(s);
    v.x *= inv; v.y *= inv; v.z *= inv; v.w *= inv;
    return v;
}

__global__ void __launch_bounds__(512)
quat_normalize_kernel(const float4* __restrict__ in,
                      float4* __restrict__ out) {
    const int T = 512;
    int base = blockIdx.x * (T * 4) + threadIdx.x;

    // Front-batch 4 independent, warp-coalesced 16B loads (MLP_p1 = 4).
    float4 a = __ldcs(&in[base]);
    float4 b = __ldcs(&in[base + T]);
    float4 c = __ldcs(&in[base + 2 * T]);
    float4 d = __ldcs(&in[base + 3 * T]);

    // Compute + store interleaved: each result retires as soon as it's ready,
    // starting the write stream early and keeping register pressure low.
    a = norm_quat(a);
    __stcs(&out[base], a);
    b = norm_quat(b);
    __stcs(&out[base + T], b);
    c = norm_quat(c);
    __stcs(&out[base + 2 * T], c);
    d = norm_quat(d);
    __stcs(&out[base + 3 * T], d);
}

// Bounds-checked fallback for non-multiple sizes (unused for 2^24 quats).
__global__ void __launch_bounds__(256)
quat_normalize_tail_kernel(const float4* __restrict__ in,
                           float4* __restrict__ out,
                           int n_quat) {
    int i = blockIdx.x * blockDim.x + threadIdx.x;
    if (i < n_quat) out[i] = norm_quat(__ldcs(&in[i]));
}

extern "C" void kernel_launch(void* const* d_in, const int* in_sizes, int n_in,
                              void* d_out, int out_size) {
    const float4* x = (const float4*)d_in[0];
    float4* y = (float4*)d_out;
    int n_quat = in_sizes[0] / 4;   // 16,777,216

    const int threads = 512;
    const int per_block = threads * 4;  // 2048 quats/block

    if (n_quat % per_block == 0) {
        quat_normalize_kernel<<<n_quat / per_block, threads>>>(x, y);  // 8192 blocks
    } else {
        int main_blocks = n_quat / per_block;
        if (main_blocks > 0)
            quat_normalize_kernel<<<main_blocks, threads>>>(x, y);
        int done = main_blocks * per_block;
        int rem = n_quat - done;
        if (rem > 0)
            quat_normalize_tail_kernel<<<(rem + 255) / 256, 256>>>(
                x + done, y + done, rem);
    }
}